// round 8
// baseline (speedup 1.0000x reference)
#include <cuda_runtime.h>
#include <cuda_fp16.h>

#define NT   256
#define SEQ  1024
#define NB   64

// Precomputed exp(transitions) packed by row-pairs:
// g_Epack[k*NT + j] = half2( exp(T[2k][j]), exp(T[2k+1][j]) )
__device__ __half2 g_Epack[128 * NT];

// Runtime dtype-layout flags (harness may widen bool->int32; JAX demotes int64->int32).
__device__ int g_tag_shift;   // 0: tags int32; 1: tags int64 (read low word)
__device__ int g_msk_shift;   // 0: mask uint8; 2: mask int32 (read LSB byte)

// Warp max of a POSITIVE float via integer redux (bit pattern monotone for x>0).
__device__ __forceinline__ float redux_max_pos(float v) {
    unsigned int r;
    asm volatile("redux.sync.max.u32 %0, %1, 0xffffffff;"
                 : "=r"(r) : "r"(__float_as_uint(v)));
    return __uint_as_float(r);
}

// Warp max of an arbitrary float: monotone map to u32, redux, map back.
__device__ __forceinline__ float redux_max_any(float v) {
    unsigned int b = __float_as_uint(v);
    unsigned int k = ((int)b < 0) ? ~b : (b | 0x80000000u);
    unsigned int r;
    asm volatile("redux.sync.max.u32 %0, %1, 0xffffffff;" : "=r"(r) : "r"(k));
    return __uint_as_float(((int)r < 0) ? (r & 0x7FFFFFFFu) : ~r);
}

__global__ void crf_detect_kernel(const int* __restrict__ tags_raw,
                                  const unsigned int* __restrict__ mask_raw) {
    __shared__ int s_odd, s_up;
    int t = threadIdx.x;            // 256 threads
    if (t == 0) { s_odd = 0; s_up = 0; }
    __syncthreads();
    int any_odd = 0;
    for (int i = t; i < 512; i += 256) any_odd |= tags_raw[2 * i + 1];
    int upper = 0;
    for (int i = t; i < 1024; i += 256) upper |= (int)(mask_raw[i] & 0xFFFFFF00u);
#pragma unroll
    for (int off = 16; off > 0; off >>= 1) {
        any_odd |= __shfl_xor_sync(0xffffffffu, any_odd, off);
        upper   |= __shfl_xor_sync(0xffffffffu, upper, off);
    }
    if ((t & 31) == 0) { atomicOr(&s_odd, any_odd); atomicOr(&s_up, upper); }
    __syncthreads();
    if (t == 0) {
        g_tag_shift = (s_odd == 0) ? 1 : 0;
        g_msk_shift = (s_up  == 0) ? 2 : 0;
    }
}

__global__ void crf_exp_kernel(const float* __restrict__ trans) {
    int idx = blockIdx.x * blockDim.x + threadIdx.x;  // 0 .. 32767
    int k = idx >> 8;
    int j = idx & (NT - 1);
    float e0 = __expf(trans[(2 * k) * NT + j]);
    float e1 = __expf(trans[(2 * k + 1) * NT + j]);
    g_Epack[idx] = __floats2half2_rn(e0, e1);
}

__global__ __launch_bounds__(256, 1)
void crf_fwd_kernel(const float* __restrict__ inputs,
                    const void* __restrict__ tags_v,
                    const void* __restrict__ mask_v,
                    const float* __restrict__ trans,
                    const float* __restrict__ start_t,
                    const float* __restrict__ stop_t,
                    float* __restrict__ out) {
    __shared__ __align__(16) __half aexp_h[NT];
    __shared__ __align__(16) float wred[8];

    const int j    = threadIdx.x;
    const int b    = blockIdx.x;
    const int lane = j & 31;
    const int wid  = j >> 5;

    const int tsh = g_tag_shift;
    const int msh = g_msk_shift;
    const int*           tg32 = (const int*)tags_v;
    const unsigned char* mk8  = (const unsigned char*)mask_v;

    // This thread's column of E in registers: 128 half2 = rows (2k,2k+1), col j.
    __half2 Ereg[128];
#pragma unroll
    for (int k = 0; k < 128; ++k) Ereg[k] = g_Epack[k * NT + j];

    const float* x = inputs + (size_t)b * SEQ * NT;
    const size_t rowbase = (size_t)b * SEQ;

    // ---- init: alpha0 = start + x0; a = exp(alpha0 - M0); C = M0 ----
    float alpha0 = start_t[j] + x[j];
    {
        float m = redux_max_any(alpha0);
        if (lane == 0) wred[wid] = m;
    }
    __syncthreads();
    float M0;
    {
        float4 w0 = *reinterpret_cast<const float4*>(wred);
        float4 w1 = *reinterpret_cast<const float4*>(wred + 4);
        M0 = fmaxf(fmaxf(fmaxf(w0.x, w0.y), fmaxf(w0.z, w0.w)),
                   fmaxf(fmaxf(w1.x, w1.y), fmaxf(w1.z, w1.w)));
    }
    __half a_self = __float2half_rn(__expf(alpha0 - M0));
    aexp_h[j] = a_self;
    float Csum = M0;            // block-uniform accumulation
    __syncthreads();

    float emit = x[NT + j];     // prefetch t=1

    for (int t = 1; t < SEQ; ++t) {
        // off-chain work for this step
        float eemit = __expf(emit);
        unsigned int msk = mk8[(rowbase + t) << msh];
        int tn = (t + 1 < SEQ) ? (t + 1) : (SEQ - 1);
        float emit_nx = x[(size_t)tn * NT + j];   // prefetch next step

        // ---- s_j = sum_i a_i * E[i][j] : fp16 HFMA2, 4 accumulators ----
        __half2 acc0 = __floats2half2_rn(0.f, 0.f);
        __half2 acc1 = acc0, acc2 = acc0, acc3 = acc0;
        const uint4* A4 = reinterpret_cast<const uint4*>(aexp_h);
#pragma unroll
        for (int c = 0; c < 32; ++c) {
            uint4 av = A4[c];
            acc0 = __hfma2(*reinterpret_cast<__half2*>(&av.x), Ereg[4 * c + 0], acc0);
            acc1 = __hfma2(*reinterpret_cast<__half2*>(&av.y), Ereg[4 * c + 1], acc1);
            acc2 = __hfma2(*reinterpret_cast<__half2*>(&av.z), Ereg[4 * c + 2], acc2);
            acc3 = __hfma2(*reinterpret_cast<__half2*>(&av.w), Ereg[4 * c + 3], acc3);
        }
        __half2 accA = __hadd2(__hadd2(acc0, acc1), __hadd2(acc2, acc3));
        float s = __half2float(__hadd(__low2half(accA), __high2half(accA)));

        // u_j = s_j * exp(emit_j)  (strictly positive) ; normalize by block max
        float u = s * eemit;
        float um = redux_max_pos(u);
        if (lane == 0) wred[wid] = um;
        __syncthreads();
        float4 w0 = *reinterpret_cast<const float4*>(wred);
        float4 w1 = *reinterpret_cast<const float4*>(wred + 4);
        float U = fmaxf(fmaxf(fmaxf(w0.x, w0.y), fmaxf(w0.z, w0.w)),
                        fmaxf(fmaxf(w1.x, w1.y), fmaxf(w1.z, w1.w)));

        __half anew = __float2half_rn(__fdividef(u, U));
        a_self = msk ? anew : a_self;          // mask==0: freeze (alpha = C + log a invariant)
        aexp_h[j] = a_self;
        Csum += msk ? __logf(U) : 0.f;         // off-chain scalar accumulation
        __syncthreads();

        emit = emit_nx;
    }

    float alpha = Csum + __logf(__half2float(a_self));

    // ---- denominator: logsumexp_j(alpha_j + stop_j) ----
    float v = alpha + stop_t[j];
    {
        float m = redux_max_any(v);
        if (lane == 0) wred[wid] = m;
    }
    __syncthreads();
    float Md;
    {
        float4 w0 = *reinterpret_cast<const float4*>(wred);
        float4 w1 = *reinterpret_cast<const float4*>(wred + 4);
        Md = fmaxf(fmaxf(fmaxf(w0.x, w0.y), fmaxf(w0.z, w0.w)),
                   fmaxf(fmaxf(w1.x, w1.y), fmaxf(w1.z, w1.w)));
    }
    __syncthreads();
    float e = __expf(v - Md);
#pragma unroll
    for (int off = 16; off > 0; off >>= 1)
        e += __shfl_xor_sync(0xffffffffu, e, off);
    if (lane == 0) wred[wid] = e;
    __syncthreads();
    float tot = 0.f;
#pragma unroll
    for (int w = 0; w < 8; ++w) tot += wred[w];
    float denom = Md + __logf(tot);

    // ---- numerator (gather score) ----
    float part = 0.f;
    for (int t = j; t < SEQ; t += 256) {
        int   tag = tg32[(rowbase + t) << tsh];
        float mf  = mk8[(rowbase + t) << msh] ? 1.f : 0.f;
        if (t == 0) part += start_t[tag];
        else {
            int ptag = tg32[(rowbase + t - 1) << tsh];
            part += trans[ptag * NT + tag] * mf;
        }
        float em = x[(size_t)t * NT + tag];
        if (t < SEQ - 1) part += em * mf;
        else             part += (stop_t[tag] + em) * mf;
    }
#pragma unroll
    for (int off = 16; off > 0; off >>= 1)
        part += __shfl_xor_sync(0xffffffffu, part, off);
    __syncthreads();
    if (lane == 0) wred[wid] = part;
    __syncthreads();
    if (j == 0) {
        float num = 0.f;
#pragma unroll
        for (int w = 0; w < 8; ++w) num += wred[w];
        out[b] = num - denom;
    }
}

extern "C" void kernel_launch(void* const* d_in, const int* in_sizes, int n_in,
                              void* d_out, int out_size) {
    const float* inputs  = (const float*)d_in[0];
    const void*  tags    = d_in[1];
    const void*  mask    = d_in[2];
    const float* trans   = (const float*)d_in[3];
    const float* start_t = (const float*)d_in[4];
    const float* stop_t  = (const float*)d_in[5];
    float*       out     = (float*)d_out;

    crf_detect_kernel<<<1, 256>>>((const int*)tags, (const unsigned int*)mask);
    crf_exp_kernel<<<128, 256>>>(trans);
    crf_fwd_kernel<<<NB, 256>>>(inputs, tags, mask, trans, start_t, stop_t, out);
}

// round 15
// speedup vs baseline: 1.3750x; 1.3750x over previous
#include <cuda_runtime.h>
#include <cuda_bf16.h>

#define NT   256
#define SEQ  1024
#define NB   64

// Precomputed exp(transitions) packed by row-pairs (bf16):
// g_Epack[k*NT + j] = bf162( exp(T[2k][j]), exp(T[2k+1][j]) )
__device__ __nv_bfloat162 g_Epack[128 * NT];

// Runtime dtype-layout flags (harness may widen bool->int32; JAX demotes int64->int32).
__device__ int g_tag_shift;   // 0: tags int32; 1: tags int64 (read low word)
__device__ int g_msk_shift;   // 0: mask uint8; 2: mask int32 (read LSB byte)

// Warp max of a POSITIVE float via integer redux (bit pattern monotone for x>0).
// (redux.sync.*.u32 is sm_80+; the .f32 variant is NOT supported on sm_103.)
__device__ __forceinline__ float redux_max_pos(float v) {
    unsigned int r;
    asm volatile("redux.sync.max.u32 %0, %1, 0xffffffff;"
                 : "=r"(r) : "r"(__float_as_uint(v)));
    return __uint_as_float(r);
}

// Warp max of an arbitrary float: monotone map to u32, redux, map back.
__device__ __forceinline__ float redux_max_any(float v) {
    unsigned int b = __float_as_uint(v);
    unsigned int k = ((int)b < 0) ? ~b : (b | 0x80000000u);
    unsigned int r;
    asm volatile("redux.sync.max.u32 %0, %1, 0xffffffff;" : "=r"(r) : "r"(k));
    return __uint_as_float(((int)r < 0) ? (r & 0x7FFFFFFFu) : ~r);
}

__global__ void crf_detect_kernel(const int* __restrict__ tags_raw,
                                  const unsigned int* __restrict__ mask_raw) {
    __shared__ int s_odd, s_up;
    int t = threadIdx.x;            // 256 threads
    if (t == 0) { s_odd = 0; s_up = 0; }
    __syncthreads();
    int any_odd = 0;
    for (int i = t; i < 512; i += 256) any_odd |= tags_raw[2 * i + 1];
    int upper = 0;
    for (int i = t; i < 1024; i += 256) upper |= (int)(mask_raw[i] & 0xFFFFFF00u);
#pragma unroll
    for (int off = 16; off > 0; off >>= 1) {
        any_odd |= __shfl_xor_sync(0xffffffffu, any_odd, off);
        upper   |= __shfl_xor_sync(0xffffffffu, upper, off);
    }
    if ((t & 31) == 0) { atomicOr(&s_odd, any_odd); atomicOr(&s_up, upper); }
    __syncthreads();
    if (t == 0) {
        g_tag_shift = (s_odd == 0) ? 1 : 0;
        g_msk_shift = (s_up  == 0) ? 2 : 0;
    }
}

__global__ void crf_exp_kernel(const float* __restrict__ trans) {
    int idx = blockIdx.x * blockDim.x + threadIdx.x;  // 0 .. 32767
    int k = idx >> 8;
    int j = idx & (NT - 1);
    float e0 = __expf(trans[(2 * k) * NT + j]);
    float e1 = __expf(trans[(2 * k + 1) * NT + j]);
    g_Epack[idx] = __floats2bfloat162_rn(e0, e1);
}

__global__ __launch_bounds__(256, 1)
void crf_fwd_kernel(const float* __restrict__ inputs,
                    const void* __restrict__ tags_v,
                    const void* __restrict__ mask_v,
                    const float* __restrict__ trans,
                    const float* __restrict__ start_t,
                    const float* __restrict__ stop_t,
                    float* __restrict__ out) {
    // Double-buffered normalized alpha (bf16) and per-warp max scratch:
    // one __syncthreads per step (write buf[t&1] -> read next step), no WAR barrier.
    __shared__ __align__(16) __nv_bfloat16 abuf[2][NT];
    __shared__ __align__(16) float wred[2][8];

    const int j    = threadIdx.x;
    const int b    = blockIdx.x;
    const int lane = j & 31;
    const int wid  = j >> 5;

    const int tsh = g_tag_shift;
    const int msh = g_msk_shift;
    const int*           tg32 = (const int*)tags_v;
    const unsigned char* mk8  = (const unsigned char*)mask_v;

    // This thread's column of E in registers: 128 bf162 = rows (2k,2k+1), col j.
    __nv_bfloat162 Ereg[128];
#pragma unroll
    for (int k = 0; k < 128; ++k) Ereg[k] = g_Epack[k * NT + j];

    const float* x = inputs + (size_t)b * SEQ * NT;
    const size_t rowbase = (size_t)b * SEQ;

    // ---- init: alpha0 = start + x0; a = exp(alpha0 - M0); Csum = M0 ----
    float alpha0 = start_t[j] + x[j];
    {
        float m = redux_max_any(alpha0);
        if (lane == 0) wred[1][wid] = m;
    }
    __syncthreads();
    float M0;
    {
        float4 w0 = *reinterpret_cast<const float4*>(wred[1]);
        float4 w1 = *reinterpret_cast<const float4*>(wred[1] + 4);
        M0 = fmaxf(fmaxf(fmaxf(w0.x, w0.y), fmaxf(w0.z, w0.w)),
                   fmaxf(fmaxf(w1.x, w1.y), fmaxf(w1.z, w1.w)));
    }
    __nv_bfloat16 a_self = __float2bfloat16(__expf(alpha0 - M0));
    abuf[0][j] = a_self;
    if (j < 8) wred[0][j] = 1.0f;   // seed: divisor for step 1 = 32*sqrt(1) = 32
    float Csum = M0;
    __syncthreads();

    float emit = x[NT + j];           // prefetch t = 1

#pragma unroll 2
    for (int t = 1; t < SEQ; ++t) {
        const int rb = (t + 1) & 1;   // holds a (and warp maxima) from step t-1
        const int wb = t & 1;

        // ---- off-chain: DAMPED stale divisor V = 32 * sqrt(U_{t-1}) ----
        // Full stale correction (V = K*U_{t-1}) has poles e^{+-i pi/3} on the
        // unit circle -> resonant oscillation of (C - max alpha) that NaN'ed
        // R9/R11. The sqrt (gain 1/2) moves poles to |z|=0.707 (damped);
        // steady offset d* = 2*log32 - E[dm] stays O(5), noise sigma ~4, and
        // the bf16 matvec range (e^+-88) absorbs any residual excursion.
        float4 w0 = *reinterpret_cast<const float4*>(wred[rb]);
        float4 w1 = *reinterpret_cast<const float4*>(wred[rb] + 4);
        float U = fmaxf(fmaxf(fmaxf(w0.x, w0.y), fmaxf(w0.z, w0.w)),
                        fmaxf(fmaxf(w1.x, w1.y), fmaxf(w1.z, w1.w)));
        float rcpV = rsqrtf(U) * 0.03125f;            // 1/(32*sqrt(U))
        float logV = 3.4657359028f + 0.5f * __logf(U); // log32 + log(U)/2

        // off-chain per-step loads / exp
        float eemit = __expf(emit);
        unsigned int msk = mk8[(rowbase + t) << msh];
        int tn = (t + 1 < SEQ) ? (t + 1) : (SEQ - 1);
        float emit_nx = x[(size_t)tn * NT + j];   // prefetch next step

        // ---- s_j = sum_i a_i * E[i][j] : bf16 HFMA2, 4 accumulators ----
        __nv_bfloat162 acc0 = __floats2bfloat162_rn(0.f, 0.f);
        __nv_bfloat162 acc1 = acc0, acc2 = acc0, acc3 = acc0;
        const uint4* A4 = reinterpret_cast<const uint4*>(abuf[rb]);
#pragma unroll
        for (int c = 0; c < 32; ++c) {
            uint4 av = A4[c];
            acc0 = __hfma2(*reinterpret_cast<__nv_bfloat162*>(&av.x), Ereg[4 * c + 0], acc0);
            acc1 = __hfma2(*reinterpret_cast<__nv_bfloat162*>(&av.y), Ereg[4 * c + 1], acc1);
            acc2 = __hfma2(*reinterpret_cast<__nv_bfloat162*>(&av.z), Ereg[4 * c + 2], acc2);
            acc3 = __hfma2(*reinterpret_cast<__nv_bfloat162*>(&av.w), Ereg[4 * c + 3], acc3);
        }
        __nv_bfloat162 accA = __hadd2(__hadd2(acc0, acc1), __hadd2(acc2, acc3));
        float2 fA = __bfloat1622float2(accA);
        float s = fA.x + fA.y;

        // u_j = s_j * exp(emit_j)  (strictly positive)
        float u = s * eemit;

        // tail (parallel paths): warp max for NEXT step's divisor | a = u/V
        float um = redux_max_pos(u);
        if (lane == 0) wred[wb][wid] = um;

        __nv_bfloat16 anew = __float2bfloat16(u * rcpV);
        a_self = msk ? anew : a_self;       // mask==0: freeze (alpha = Csum + log a)
        abuf[wb][j] = a_self;
        Csum += msk ? logV : 0.f;           // same divisor -> invariant exact

        __syncthreads();
        emit = emit_nx;
    }

    float alpha = Csum + __logf(__bfloat162float(a_self));

    // ---- denominator: logsumexp_j(alpha_j + stop_j) ----
    float v = alpha + stop_t[j];
    {
        float m = redux_max_any(v);
        if (lane == 0) wred[0][wid] = m;
    }
    __syncthreads();
    float Md;
    {
        float4 w0 = *reinterpret_cast<const float4*>(wred[0]);
        float4 w1 = *reinterpret_cast<const float4*>(wred[0] + 4);
        Md = fmaxf(fmaxf(fmaxf(w0.x, w0.y), fmaxf(w0.z, w0.w)),
                   fmaxf(fmaxf(w1.x, w1.y), fmaxf(w1.z, w1.w)));
    }
    __syncthreads();
    float e = __expf(v - Md);
#pragma unroll
    for (int off = 16; off > 0; off >>= 1)
        e += __shfl_xor_sync(0xffffffffu, e, off);
    if (lane == 0) wred[0][wid] = e;
    __syncthreads();
    float tot = 0.f;
#pragma unroll
    for (int w = 0; w < 8; ++w) tot += wred[0][w];
    float denom = Md + __logf(tot);

    // ---- numerator (gather score) ----
    float part = 0.f;
    for (int t = j; t < SEQ; t += 256) {
        int   tag = tg32[(rowbase + t) << tsh];
        float mf  = mk8[(rowbase + t) << msh] ? 1.f : 0.f;
        if (t == 0) part += start_t[tag];
        else {
            int ptag = tg32[(rowbase + t - 1) << tsh];
            part += trans[ptag * NT + tag] * mf;
        }
        float em = x[(size_t)t * NT + tag];
        if (t < SEQ - 1) part += em * mf;
        else             part += (stop_t[tag] + em) * mf;
    }
#pragma unroll
    for (int off = 16; off > 0; off >>= 1)
        part += __shfl_xor_sync(0xffffffffu, part, off);
    __syncthreads();
    if (lane == 0) wred[0][wid] = part;
    __syncthreads();
    if (j == 0) {
        float num = 0.f;
#pragma unroll
        for (int w = 0; w < 8; ++w) num += wred[0][w];
        out[b] = num - denom;
    }
}

extern "C" void kernel_launch(void* const* d_in, const int* in_sizes, int n_in,
                              void* d_out, int out_size) {
    const float* inputs  = (const float*)d_in[0];
    const void*  tags    = d_in[1];
    const void*  mask    = d_in[2];
    const float* trans   = (const float*)d_in[3];
    const float* start_t = (const float*)d_in[4];
    const float* stop_t  = (const float*)d_in[5];
    float*       out     = (float*)d_out;

    crf_detect_kernel<<<1, 256>>>((const int*)tags, (const unsigned int*)mask);
    crf_exp_kernel<<<128, 256>>>(trans);
    crf_fwd_kernel<<<NB, 256>>>(inputs, tags, mask, trans, start_t, stop_t, out);
}